// round 1
// baseline (speedup 1.0000x reference)
#include <cuda_runtime.h>
#include <math.h>

#define DD 2048
#define LL 128
#define BB 64

// Scratch (no device allocation allowed)
__device__ float  g_wl[DD];
__device__ float  g_wr[DD];
__device__ float  g_dj[BB * LL];
__device__ float  g_ek[BB * LL];
__device__ double g_sum;
__device__ int    g_cnt;
__device__ float  g_db;

// ---------------------------------------------------------------------------
// Kernel 1: precompute column-diff weight vectors + reset accumulators.
// wl[d] = W[d,1]-W[d,0]   (W is row-major [2D, 2])
// wr[d] = W[D+d,1]-W[D+d,0]
// ---------------------------------------------------------------------------
__global__ void prep_kernel(const float* __restrict__ W,
                            const float* __restrict__ bias) {
    int d = blockIdx.x * blockDim.x + threadIdx.x;
    if (d < DD) {
        float2 a = *(const float2*)(W + 2 * d);
        float2 r = *(const float2*)(W + 2 * (DD + d));
        g_wl[d] = a.y - a.x;
        g_wr[d] = r.y - r.x;
    }
    if (d == 0) {
        g_db  = bias[1] - bias[0];
        g_sum = 0.0;
        g_cnt = 0;
    }
}

// ---------------------------------------------------------------------------
// Kernel 2: one warp per (b,l) row. Two dot products of length 2048 against
// g_wl / g_wr. 67 MB streamed from HBM — this is the whole cost of the kernel.
// ---------------------------------------------------------------------------
__global__ __launch_bounds__(256) void rowdot_kernel(const float* __restrict__ enc) {
    int gwarp = (blockIdx.x * blockDim.x + threadIdx.x) >> 5;
    int lane  = threadIdx.x & 31;
    if (gwarp >= BB * LL) return;

    const float4* e4  = (const float4*)(enc + (size_t)gwarp * DD);
    const float4* wl4 = (const float4*)g_wl;
    const float4* wr4 = (const float4*)g_wr;

    float sd = 0.f, se = 0.f;
#pragma unroll
    for (int it = 0; it < DD / 4 / 32; ++it) {   // 16 iterations, fully unrolled
        int i = lane + it * 32;
        float4 e = e4[i];
        float4 a = wl4[i];
        float4 r = wr4[i];
        sd += e.x * a.x + e.y * a.y + e.z * a.z + e.w * a.w;
        se += e.x * r.x + e.y * r.y + e.z * r.z + e.w * r.w;
    }
#pragma unroll
    for (int o = 16; o; o >>= 1) {
        sd += __shfl_down_sync(0xFFFFFFFFu, sd, o);
        se += __shfl_down_sync(0xFFFFFFFFu, se, o);
    }
    if (lane == 0) {
        g_dj[gwarp] = sd;
        g_ek[gwarp] = se;
    }
}

// ---------------------------------------------------------------------------
// Kernel 3: one block per batch element. Reduce mask -> length, stage dj/ek
// in shared, sweep valid pairs (k < j < len):
//   s   = dj[j] + ek[k] + db
//   nll = softplus(s) if label==0 (k != j-1), else softplus(-s)
// ---------------------------------------------------------------------------
__device__ __forceinline__ float softplus_stable(float x) {
    return fmaxf(x, 0.f) + log1pf(expf(-fabsf(x)));
}

__global__ __launch_bounds__(256) void pair_kernel(const int* __restrict__ mask) {
    __shared__ float s_dj[LL];
    __shared__ float s_ek[LL];
    __shared__ float s_red[256];
    __shared__ int   s_len;

    int b   = blockIdx.x;
    int tid = threadIdx.x;

    // turn length = sum(mask[b, :])
    float m = (tid < LL) ? (float)mask[b * LL + tid] : 0.f;
    s_red[tid] = m;
    __syncthreads();
#pragma unroll
    for (int o = 128; o; o >>= 1) {
        if (tid < o) s_red[tid] += s_red[tid + o];
        __syncthreads();
    }
    if (tid == 0) s_len = (int)(s_red[0] + 0.5f);

    if (tid < LL) {
        s_dj[tid] = g_dj[b * LL + tid];
        s_ek[tid] = g_ek[b * LL + tid];
    }
    __syncthreads();

    int   len = s_len;
    float db  = g_db;
    float acc = 0.f;
    for (int j = 1; j < len; ++j) {
        float dj = s_dj[j];
        for (int k = tid; k < j; k += 256) {
            float x = dj + s_ek[k] + db;
            if (k == j - 1) x = -x;     // label 1 -> softplus(-(z1-z0))
            acc += softplus_stable(x);
        }
    }

    s_red[tid] = acc;
    __syncthreads();
#pragma unroll
    for (int o = 128; o; o >>= 1) {
        if (tid < o) s_red[tid] += s_red[tid + o];
        __syncthreads();
    }
    if (tid == 0) {
        atomicAdd(&g_sum, (double)s_red[0]);
        atomicAdd(&g_cnt, len * (len - 1) / 2);
    }
}

// ---------------------------------------------------------------------------
// Kernel 4: finalize scalar loss.
// ---------------------------------------------------------------------------
__global__ void finalize_kernel(float* __restrict__ out) {
    int c = g_cnt;
    if (c < 1) c = 1;
    out[0] = (float)(g_sum / (double)c);
}

extern "C" void kernel_launch(void* const* d_in, const int* in_sizes, int n_in,
                              void* d_out, int out_size) {
    const float* enc  = (const float*)d_in[0];  // [64,128,2048] f32
    const int*   mask = (const int*)d_in[1];    // [64,128] i32
    const float* W    = (const float*)d_in[2];  // [4096,2] f32
    const float* bias = (const float*)d_in[3];  // [2] f32
    float* out = (float*)d_out;

    prep_kernel<<<(DD + 255) / 256, 256>>>(W, bias);
    rowdot_kernel<<<(BB * LL * 32 + 255) / 256, 256>>>(enc);
    pair_kernel<<<BB, 256>>>(mask);
    finalize_kernel<<<1, 1>>>(out);
}

// round 2
// speedup vs baseline: 1.0568x; 1.0568x over previous
#include <cuda_runtime.h>
#include <math.h>

#define DD 2048
#define LL 128
#define BB 64
#define NTHR 256

// Scratch (no device allocation allowed)
__device__ float    g_dj[BB * LL];
__device__ float    g_ek[BB * LL];
__device__ float    g_psum[BB];
__device__ int      g_pcnt[BB];
__device__ unsigned g_bar;    // monotonic grid-barrier counter (graph-replay safe)
__device__ unsigned g_done;   // monotonic phase-2 completion counter

__device__ __forceinline__ float softplus_stable(float x) {
    return fmaxf(x, 0.f) + log1pf(expf(-fabsf(x)));
}

__global__ __launch_bounds__(NTHR) void dli_fused_kernel(
    const float* __restrict__ enc,   // [64,128,2048]
    const int*   __restrict__ mask,  // [64,128]
    const float* __restrict__ W,     // [4096,2] row-major
    const float* __restrict__ bias,  // [2]
    float* __restrict__ out)
{
    __shared__ float s_wl[DD];
    __shared__ float s_wr[DD];
    __shared__ float s_red[NTHR];
    __shared__ float s_dj[LL];
    __shared__ float s_ek[LL];
    __shared__ int   s_len;

    const int tid  = threadIdx.x;
    const int nblk = gridDim.x;

    // ---- Phase 0: column-diff weight vectors in smem (per block) ----------
    for (int d = tid; d < DD; d += NTHR) {
        float2 a = *(const float2*)(W + 2 * d);
        float2 r = *(const float2*)(W + 2 * (DD + d));
        s_wl[d] = a.y - a.x;
        s_wr[d] = r.y - r.x;
    }
    __syncthreads();

    // ---- Phase 1: warp-per-row dual dot products (the 67 MB HBM stream) ---
    const int warp = tid >> 5;
    const int lane = tid & 31;
    const float4* wl4 = (const float4*)s_wl;
    const float4* wr4 = (const float4*)s_wr;

    for (int row = blockIdx.x * (NTHR / 32) + warp; row < BB * LL;
         row += nblk * (NTHR / 32)) {
        const float4* e4 = (const float4*)(enc + (size_t)row * DD);
        float sd = 0.f, se = 0.f;
#pragma unroll
        for (int it = 0; it < DD / 4 / 32; ++it) {   // 16 independent float4 loads
            int i = lane + it * 32;
            float4 e = e4[i];
            float4 a = wl4[i];
            float4 r = wr4[i];
            sd += e.x * a.x + e.y * a.y + e.z * a.z + e.w * a.w;
            se += e.x * r.x + e.y * r.y + e.z * r.z + e.w * r.w;
        }
#pragma unroll
        for (int o = 16; o; o >>= 1) {
            sd += __shfl_down_sync(0xFFFFFFFFu, sd, o);
            se += __shfl_down_sync(0xFFFFFFFFu, se, o);
        }
        if (lane == 0) {
            g_dj[row] = sd;
            g_ek[row] = se;
        }
    }

    // ---- Grid barrier (monotonic counter: no reset race across replays) ---
    __syncthreads();
    if (tid == 0) {
        __threadfence();
        unsigned old    = atomicAdd(&g_bar, 1u);
        unsigned target = (old / (unsigned)nblk + 1u) * (unsigned)nblk;
        while (*(volatile unsigned*)&g_bar < target) { }
        __threadfence();
    }
    __syncthreads();

    // ---- Phase 2: blocks 0..63 — pair softplus sweep per batch ------------
    if (blockIdx.x >= BB) return;
    const int b = blockIdx.x;

    // turn length = sum(mask[b,:])
    float m = (tid < LL) ? (float)mask[b * LL + tid] : 0.f;
    s_red[tid] = m;
    __syncthreads();
#pragma unroll
    for (int o = NTHR / 2; o; o >>= 1) {
        if (tid < o) s_red[tid] += s_red[tid + o];
        __syncthreads();
    }
    if (tid == 0) s_len = (int)(s_red[0] + 0.5f);

    if (tid < LL) {
        s_dj[tid] = __ldcg(&g_dj[b * LL + tid]);   // bypass L1: cross-SM data
        s_ek[tid] = __ldcg(&g_ek[b * LL + tid]);
    }
    __syncthreads();

    const int   len = s_len;
    const float db  = bias[1] - bias[0];
    float acc = 0.f;
    for (int j = 1; j < len; ++j) {
        float dj = s_dj[j];
        for (int k = tid; k < j; k += NTHR) {
            float x = dj + s_ek[k] + db;
            if (k == j - 1) x = -x;         // label 1 -> softplus(-(z1-z0))
            acc += softplus_stable(x);
        }
    }

    s_red[tid] = acc;
    __syncthreads();
#pragma unroll
    for (int o = NTHR / 2; o; o >>= 1) {
        if (tid < o) s_red[tid] += s_red[tid + o];
        __syncthreads();
    }

    // Deterministic per-batch partials; last finishing block finalizes.
    if (tid == 0) {
        __stcg(&g_psum[b], s_red[0]);
        __stcg(&g_pcnt[b], len * (len - 1) / 2);
        __threadfence();
        unsigned old = atomicAdd(&g_done, 1u);
        if ((old % (unsigned)BB) == (unsigned)(BB - 1)) {
            __threadfence();
            double s = 0.0;
            int    c = 0;
            for (int i = 0; i < BB; ++i) {
                s += (double)__ldcg(&g_psum[i]);
                c += __ldcg(&g_pcnt[i]);
            }
            if (c < 1) c = 1;
            out[0] = (float)(s / (double)c);
        }
    }
}

extern "C" void kernel_launch(void* const* d_in, const int* in_sizes, int n_in,
                              void* d_out, int out_size) {
    const float* enc  = (const float*)d_in[0];  // [64,128,2048] f32
    const int*   mask = (const int*)d_in[1];    // [64,128] i32
    const float* W    = (const float*)d_in[2];  // [4096,2] f32
    const float* bias = (const float*)d_in[3];  // [2] f32
    float* out = (float*)d_out;

    int sm = 148;
    cudaDeviceGetAttribute(&sm, cudaDevAttrMultiProcessorCount, 0);
    if (sm > 1024) sm = 1024;           // paranoia bound
    if (sm < BB)   sm = BB;             // phase 2 needs >= 64 blocks

    dli_fused_kernel<<<sm, NTHR>>>(enc, mask, W, bias, out);
}